// round 1
// baseline (speedup 1.0000x reference)
#include <cuda_runtime.h>
#include <cuda_bf16.h>
#include <math.h>

#define NROW 8192
#define DDIM 512
#define BHALF 4096
#define NT 128                 // 8192 / 64 tiles
#define NPAIRS (NT*(NT+1)/2)   // 8256
#define BK 16
#define NK (DDIM/BK)           // 32

__device__ float  g_sq[NROW];
__device__ float  g_colsum[DDIM];
__device__ float  g_totsq;
__device__ double g_acc[3];    // 0: XX, 1: YY, 2: XY+YX
__device__ float  g_negK;      // -log2(e)/bw

// ---------------------------------------------------------------- init
__global__ void k_init() {
    int t = threadIdx.x;
    if (t < DDIM) g_colsum[t] = 0.f;
    if (t == 0) {
        g_totsq = 0.f;
        g_acc[0] = 0.0; g_acc[1] = 0.0; g_acc[2] = 0.0;
    }
}

// ---------------------------------------------------------------- row norms
// one warp per row; 1024 blocks x 256 threads
__global__ void k_rownorm(const float* __restrict__ src,
                          const float* __restrict__ tgt) {
    int warp = threadIdx.x >> 5, lane = threadIdx.x & 31;
    int row = blockIdx.x * 8 + warp;
    const float* base = (row < BHALF) ? src + (size_t)row * DDIM
                                      : tgt + (size_t)(row - BHALF) * DDIM;
    float s = 0.f;
#pragma unroll
    for (int ch = 0; ch < 4; ch++) {
        float4 v = *(const float4*)(base + ch * 128 + lane * 4);
        s += v.x * v.x + v.y * v.y + v.z * v.z + v.w * v.w;
    }
#pragma unroll
    for (int o = 16; o > 0; o >>= 1) s += __shfl_xor_sync(0xffffffffu, s, o);
    if (lane == 0) g_sq[row] = s;

    __shared__ float bs[8];
    if (lane == 0) bs[warp] = s;
    __syncthreads();
    if (threadIdx.x == 0) {
        float t = 0.f;
#pragma unroll
        for (int i = 0; i < 8; i++) t += bs[i];
        atomicAdd(&g_totsq, t);
    }
}

// ---------------------------------------------------------------- column sums
// 64 blocks x 256 threads; block handles 128 rows, thread owns 2 columns
__global__ void k_colsum(const float* __restrict__ src,
                         const float* __restrict__ tgt) {
    int c = threadIdx.x * 2;
    int r0 = blockIdx.x * 128;
    const float* base = (r0 < BHALF) ? src + (size_t)r0 * DDIM
                                     : tgt + (size_t)(r0 - BHALF) * DDIM;
    float s0 = 0.f, s1 = 0.f;
    for (int r = 0; r < 128; r++) {
        float2 v = *(const float2*)(base + (size_t)r * DDIM + c);
        s0 += v.x; s1 += v.y;
    }
    atomicAdd(&g_colsum[c],     s0);
    atomicAdd(&g_colsum[c + 1], s1);
}

// ---------------------------------------------------------------- bandwidth
__global__ void k_bw() {
    __shared__ double red[512];
    int t = threadIdx.x;
    double v = (double)g_colsum[t];
    red[t] = v * v;
    __syncthreads();
    for (int o = 256; o > 0; o >>= 1) {
        if (t < o) red[t] += red[t + o];
        __syncthreads();
    }
    if (t == 0) {
        double n = (double)NROW;
        double S = 2.0 * n * (double)g_totsq - 2.0 * red[0];   // sum(L2)
        double bw = S / (n * n - n) / 4.0;                     // / 2^(5//2)
        g_negK = (float)(-1.4426950408889634 / bw);            // -log2(e)/bw
    }
}

// ---------------------------------------------------------------- main fused kernel
// symmetric tile enumeration: block t -> (bi, bj), bi <= bj, 64x64 tiles
__global__ void __launch_bounds__(256)
k_mmd(const float* __restrict__ src, const float* __restrict__ tgt) {
    __shared__ float As[2][BK][68];
    __shared__ float Bs[2][BK][68];
    __shared__ float red[256];

    int t = blockIdx.x;
    // triangular decode with fixup
    int bi = (int)((2.0 * NT + 1.0 -
                    sqrt((2.0 * NT + 1.0) * (2.0 * NT + 1.0) - 8.0 * (double)t)) * 0.5);
    if (bi < 0) bi = 0;
    if (bi > NT - 1) bi = NT - 1;
    while (bi > 0 && bi * (2 * NT - bi + 1) / 2 > t) bi--;
    while ((bi + 1) * (2 * NT - bi) / 2 <= t) bi++;
    int bj = bi + (t - bi * (2 * NT - bi + 1) / 2);

    int rowA = bi * 64, rowB = bj * 64;
    const float* baseA = (rowA < BHALF) ? src + (size_t)rowA * DDIM
                                        : tgt + (size_t)(rowA - BHALF) * DDIM;
    const float* baseB = (rowB < BHALF) ? src + (size_t)rowB * DDIM
                                        : tgt + (size_t)(rowB - BHALF) * DDIM;

    int tid  = threadIdx.x;
    int lrow = tid >> 2;     // 0..63 : tile row for global load
    int seg  = tid & 3;      // 0..3  : 4-float segment within 16-col chunk
    int tx   = tid & 15;     // C-tile col group
    int ty   = tid >> 4;     // C-tile row group

    float c[4][4] = {};
    float4 ra, rb;

    // preload chunk 0
    ra = *(const float4*)(baseA + (size_t)lrow * DDIM + seg * 4);
    rb = *(const float4*)(baseB + (size_t)lrow * DDIM + seg * 4);
    As[0][seg * 4 + 0][lrow] = ra.x; As[0][seg * 4 + 1][lrow] = ra.y;
    As[0][seg * 4 + 2][lrow] = ra.z; As[0][seg * 4 + 3][lrow] = ra.w;
    Bs[0][seg * 4 + 0][lrow] = rb.x; Bs[0][seg * 4 + 1][lrow] = rb.y;
    Bs[0][seg * 4 + 2][lrow] = rb.z; Bs[0][seg * 4 + 3][lrow] = rb.w;

    for (int kt = 0; kt < NK; kt++) {
        __syncthreads();
        int cur = kt & 1;
        if (kt + 1 < NK) {
            ra = *(const float4*)(baseA + (size_t)lrow * DDIM + (kt + 1) * BK + seg * 4);
            rb = *(const float4*)(baseB + (size_t)lrow * DDIM + (kt + 1) * BK + seg * 4);
        }
#pragma unroll
        for (int k = 0; k < BK; k++) {
            float4 a = *(const float4*)&As[cur][k][ty * 4];
            float4 b = *(const float4*)&Bs[cur][k][tx * 4];
            c[0][0] += a.x * b.x; c[0][1] += a.x * b.y; c[0][2] += a.x * b.z; c[0][3] += a.x * b.w;
            c[1][0] += a.y * b.x; c[1][1] += a.y * b.y; c[1][2] += a.y * b.z; c[1][3] += a.y * b.w;
            c[2][0] += a.z * b.x; c[2][1] += a.z * b.y; c[2][2] += a.z * b.z; c[2][3] += a.z * b.w;
            c[3][0] += a.w * b.x; c[3][1] += a.w * b.y; c[3][2] += a.w * b.z; c[3][3] += a.w * b.w;
        }
        if (kt + 1 < NK) {
            int nxt = cur ^ 1;
            As[nxt][seg * 4 + 0][lrow] = ra.x; As[nxt][seg * 4 + 1][lrow] = ra.y;
            As[nxt][seg * 4 + 2][lrow] = ra.z; As[nxt][seg * 4 + 3][lrow] = ra.w;
            Bs[nxt][seg * 4 + 0][lrow] = rb.x; Bs[nxt][seg * 4 + 1][lrow] = rb.y;
            Bs[nxt][seg * 4 + 2][lrow] = rb.z; Bs[nxt][seg * 4 + 3][lrow] = rb.w;
        }
    }

    // -------- fused epilogue: L2 -> 5-bandwidth kernel sum --------
    float negK = g_negK;
    float sqi[4], sqj[4];
#pragma unroll
    for (int q = 0; q < 4; q++) {
        sqi[q] = g_sq[rowA + ty * 4 + q];
        sqj[q] = g_sq[rowB + tx * 4 + q];
    }
    float tsum = 0.f;
#pragma unroll
    for (int q = 0; q < 4; q++) {
#pragma unroll
        for (int r = 0; r < 4; r++) {
            float L2v = sqi[q] + sqj[r] - 2.f * c[q][r];
            float e;
            float arg = L2v * negK;
            asm("ex2.approx.f32 %0, %1;" : "=f"(e) : "f"(arg));
            float s5 = e;
#pragma unroll
            for (int i = 0; i < 4; i++) {
                asm("sqrt.approx.f32 %0, %1;" : "=f"(e) : "f"(e));
                s5 += e;
            }
            tsum += s5;
        }
    }

    red[tid] = tsum;
    __syncthreads();
    for (int o = 128; o > 0; o >>= 1) {
        if (tid < o) red[tid] += red[tid + o];
        __syncthreads();
    }
    if (tid == 0) {
        double w = (bi == bj) ? 1.0 : 2.0;
        int qidx = (bi < NT / 2) ? ((bj < NT / 2) ? 0 : 2) : 1;
        atomicAdd(&g_acc[qidx], w * (double)red[0]);
    }
}

// ---------------------------------------------------------------- final combine
__global__ void k_final(float* out) {
    double bb = (double)BHALF * (double)BHALF;
    out[0] = (float)((g_acc[0] + g_acc[1] - g_acc[2]) / bb);
}

// ---------------------------------------------------------------- launch
extern "C" void kernel_launch(void* const* d_in, const int* in_sizes, int n_in,
                              void* d_out, int out_size) {
    const float* src = (const float*)d_in[0];
    const float* tgt = (const float*)d_in[1];
    float* out = (float*)d_out;

    k_init<<<1, 512>>>();
    k_rownorm<<<NROW / 8, 256>>>(src, tgt);
    k_colsum<<<NROW / 128, 256>>>(src, tgt);
    k_bw<<<1, 512>>>();
    k_mmd<<<NPAIRS, 256>>>(src, tgt);
    k_final<<<1, 1>>>(out);
}

// round 3
// speedup vs baseline: 4.2301x; 4.2301x over previous
#include <cuda_runtime.h>
#include <cuda_bf16.h>
#include <math.h>
#include <stdint.h>

#define NROW 8192
#define DDIM 512
#define BHALF 4096

#define TILE 128
#define NT2 (NROW / TILE)            /* 64 */
#define NPAIR2 (NT2 * (NT2 + 1) / 2) /* 2080 */
#define BKC 32                       /* bf16 per K-chunk */
#define NCH (DDIM / BKC)             /* 16 */

/* smem layout (dynamic): sqA[128]f, sqB[128]f, red[8]f, tiles */
#define SQA_OFF 0
#define SQB_OFF 512
#define RED_OFF 1024
#define TILES_OFF 1280
#define ROW_PITCH 80                 /* 32 bf16 = 64B + 16B pad (conflict-free) */
#define MAT_BYTES (TILE * ROW_PITCH) /* 10240 */
#define AHI_OFF 0
#define ALO_OFF (MAT_BYTES)
#define BHI_OFF (2 * MAT_BYTES)
#define BLO_OFF (3 * MAT_BYTES)
#define STAGE_BYTES (4 * MAT_BYTES)  /* 40960 */
#define SMEM_TOTAL (TILES_OFF + 2 * STAGE_BYTES) /* 83200 */

__device__ float  g_sq[NROW];
__device__ float  g_colsum[DDIM];
__device__ float  g_totsq;
__device__ double g_acc[3];
__device__ float  g_negK;            /* -log2(e)/(16*bw) */
__device__ __nv_bfloat16 g_hi[NROW * DDIM];
__device__ __nv_bfloat16 g_lo[NROW * DDIM];

__device__ __forceinline__ uint32_t smem_u32(const void* p) {
    uint32_t a;
    asm("{ .reg .u64 t; cvta.to.shared.u64 t, %1; cvt.u32.u64 %0, t; }"
        : "=r"(a) : "l"(p));
    return a;
}

#define CP_ASYNC16(dst, src) \
    asm volatile("cp.async.cg.shared.global [%0], [%1], 16;" \
                 :: "r"(dst), "l"(src) : "memory")
#define CP_COMMIT() asm volatile("cp.async.commit_group;" ::: "memory")
#define CP_WAIT0()  asm volatile("cp.async.wait_group 0;" ::: "memory")

#define LDSM_X4(r, a) \
    asm volatile("ldmatrix.sync.aligned.m8n8.x4.shared.b16 {%0,%1,%2,%3}, [%4];" \
                 : "=r"((r)[0]), "=r"((r)[1]), "=r"((r)[2]), "=r"((r)[3]) : "r"(a))

#define MMA16816(acc, a, b0v, b1v) \
    asm volatile("mma.sync.aligned.m16n8k16.row.col.f32.bf16.bf16.f32 " \
                 "{%0,%1,%2,%3},{%4,%5,%6,%7},{%8,%9},{%0,%1,%2,%3};" \
                 : "+f"((acc)[0]), "+f"((acc)[1]), "+f"((acc)[2]), "+f"((acc)[3]) \
                 : "r"((a)[0]), "r"((a)[1]), "r"((a)[2]), "r"((a)[3]), \
                   "r"(b0v), "r"(b1v))

/* ---------------------------------------------------------------- init */
__global__ void k_init() {
    int t = threadIdx.x;
    if (t < DDIM) g_colsum[t] = 0.f;
    if (t == 0) {
        g_totsq = 0.f;
        g_acc[0] = 0.0; g_acc[1] = 0.0; g_acc[2] = 0.0;
    }
}

/* ---------------------------------------------------------------- split fp32 -> bf16 hi/lo */
__global__ void k_split(const float* __restrict__ src, const float* __restrict__ tgt) {
    size_t gid = (size_t)blockIdx.x * 256 + threadIdx.x;
    size_t idx = gid * 4;
    const float* p = (idx < (size_t)BHALF * DDIM) ? src + idx
                                                  : tgt + (idx - (size_t)BHALF * DDIM);
    float4 v = *(const float4*)p;
    __nv_bfloat16 h0 = __float2bfloat16(v.x);
    __nv_bfloat16 h1 = __float2bfloat16(v.y);
    __nv_bfloat16 h2 = __float2bfloat16(v.z);
    __nv_bfloat16 h3 = __float2bfloat16(v.w);
    __nv_bfloat16 l0 = __float2bfloat16(v.x - __bfloat162float(h0));
    __nv_bfloat16 l1 = __float2bfloat16(v.y - __bfloat162float(h1));
    __nv_bfloat16 l2 = __float2bfloat16(v.z - __bfloat162float(h2));
    __nv_bfloat16 l3 = __float2bfloat16(v.w - __bfloat162float(h3));
    __nv_bfloat162 hp0(h0, h1), hp1(h2, h3), lp0(l0, l1), lp1(l2, l3);
    uint2 hv, lv;
    hv.x = *(uint32_t*)&hp0; hv.y = *(uint32_t*)&hp1;
    lv.x = *(uint32_t*)&lp0; lv.y = *(uint32_t*)&lp1;
    ((uint2*)g_hi)[gid] = hv;
    ((uint2*)g_lo)[gid] = lv;
}

/* ---------------------------------------------------------------- row norms */
__global__ void k_rownorm(const float* __restrict__ src, const float* __restrict__ tgt) {
    int warp = threadIdx.x >> 5, lane = threadIdx.x & 31;
    int row = blockIdx.x * 8 + warp;
    const float* base = (row < BHALF) ? src + (size_t)row * DDIM
                                      : tgt + (size_t)(row - BHALF) * DDIM;
    float s = 0.f;
#pragma unroll
    for (int ch = 0; ch < 4; ch++) {
        float4 v = *(const float4*)(base + ch * 128 + lane * 4);
        s += v.x * v.x + v.y * v.y + v.z * v.z + v.w * v.w;
    }
#pragma unroll
    for (int o = 16; o > 0; o >>= 1) s += __shfl_xor_sync(0xffffffffu, s, o);
    if (lane == 0) g_sq[row] = s;

    __shared__ float bs[8];
    if (lane == 0) bs[warp] = s;
    __syncthreads();
    if (threadIdx.x == 0) {
        float t = 0.f;
#pragma unroll
        for (int i = 0; i < 8; i++) t += bs[i];
        atomicAdd(&g_totsq, t);
    }
}

/* ---------------------------------------------------------------- column sums */
__global__ void k_colsum(const float* __restrict__ src, const float* __restrict__ tgt) {
    int c = threadIdx.x * 2;
    int r0 = blockIdx.x * 128;
    const float* base = (r0 < BHALF) ? src + (size_t)r0 * DDIM
                                     : tgt + (size_t)(r0 - BHALF) * DDIM;
    float s0 = 0.f, s1 = 0.f;
    for (int r = 0; r < 128; r++) {
        float2 v = *(const float2*)(base + (size_t)r * DDIM + c);
        s0 += v.x; s1 += v.y;
    }
    atomicAdd(&g_colsum[c], s0);
    atomicAdd(&g_colsum[c + 1], s1);
}

/* ---------------------------------------------------------------- bandwidth */
__global__ void k_bw() {
    __shared__ double red[512];
    int t = threadIdx.x;
    double v = (double)g_colsum[t];
    red[t] = v * v;
    __syncthreads();
    for (int o = 256; o > 0; o >>= 1) {
        if (t < o) red[t] += red[t + o];
        __syncthreads();
    }
    if (t == 0) {
        double n = (double)NROW;
        double S = 2.0 * n * (double)g_totsq - 2.0 * red[0];
        double bw = S / (n * n - n) / 4.0;
        g_negK = (float)(-1.4426950408889634 / (16.0 * bw));
    }
}

/* ---------------------------------------------------------------- chunk loader (cp.async) */
__device__ __forceinline__ void issue_chunk(uint32_t stage_base, int rowA, int rowB,
                                            int kt, int tid) {
    const char* srcs[4] = {
        (const char*)(g_hi + (size_t)rowA * DDIM),
        (const char*)(g_lo + (size_t)rowA * DDIM),
        (const char*)(g_hi + (size_t)rowB * DDIM),
        (const char*)(g_lo + (size_t)rowB * DDIM)
    };
    int kbyte = kt * (BKC * 2);      /* 64 B per row per chunk */
#pragma unroll
    for (int m = 0; m < 4; m++) {
        uint32_t dbase = stage_base + m * MAT_BYTES;
#pragma unroll
        for (int i = 0; i < 2; i++) {
            int u = tid + i * 256;              /* 0..511 */
            int r = u >> 2, seg = u & 3;        /* row 0..127, 16B seg 0..3 */
            const char* src = srcs[m] + (size_t)r * (DDIM * 2) + kbyte + seg * 16;
            uint32_t dst = dbase + r * ROW_PITCH + seg * 16;
            CP_ASYNC16(dst, src);
        }
    }
    CP_COMMIT();
}

/* ---------------------------------------------------------------- main HMMA kernel */
__global__ void __launch_bounds__(256, 1) k_gemm() {
    extern __shared__ char smem[];
    int tid = threadIdx.x;
    int lane = tid & 31, wid = tid >> 5;
    int rw = wid & 3, cw = wid >> 2;

    /* triangular decode */
    int t = blockIdx.x;
    int bi = 0, rem = t;
    while (rem >= NT2 - bi) { rem -= NT2 - bi; bi++; }
    int bj = bi + rem;
    int rowA = bi * TILE, rowB = bj * TILE;

    uint32_t sbase = smem_u32(smem);
    float* sqA = (float*)(smem + SQA_OFF);
    float* sqB = (float*)(smem + SQB_OFF);
    float* red = (float*)(smem + RED_OFF);

    if (tid < TILE) {
        sqA[tid] = g_sq[rowA + tid];
        sqB[tid] = g_sq[rowB + tid];
    }

    /* ldmatrix lane address components */
    uint32_t aRow = rw * 32 + (lane & 7) + (lane & 8);
    uint32_t aColH = (lane & 16) >> 1;          /* bf16 units: 0 or 8 */
    uint32_t bN = cw * 64 + (lane & 7) + ((lane & 16) >> 1);
    uint32_t bKoff = (lane & 8);                /* bf16 units: 0 or 8 */

    float acc[2][8][4];
#pragma unroll
    for (int r = 0; r < 2; r++)
#pragma unroll
        for (int j = 0; j < 8; j++)
#pragma unroll
            for (int e = 0; e < 4; e++) acc[r][j][e] = 0.f;

    uint32_t tb = sbase + TILES_OFF;
    issue_chunk(tb, rowA, rowB, 0, tid);

    for (int kt = 0; kt < NCH; kt++) {
        CP_WAIT0();
        __syncthreads();
        if (kt + 1 < NCH)
            issue_chunk(tb + ((kt + 1) & 1) * STAGE_BYTES, rowA, rowB, kt + 1, tid);

        uint32_t S = tb + (kt & 1) * STAGE_BYTES;
#pragma unroll
        for (int ks = 0; ks < 2; ks++) {
            uint32_t k0 = ks * 16;
            uint32_t ah[2][4], al[2][4], bh[4][4], bl[4][4];
#pragma unroll
            for (int rt = 0; rt < 2; rt++) {
                uint32_t ao = (aRow + rt * 16) * ROW_PITCH + (k0 + aColH) * 2;
                LDSM_X4(ah[rt], S + AHI_OFF + ao);
                LDSM_X4(al[rt], S + ALO_OFF + ao);
            }
#pragma unroll
            for (int jp = 0; jp < 4; jp++) {
                uint32_t bo = (bN + jp * 16) * ROW_PITCH + (k0 + bKoff) * 2;
                LDSM_X4(bh[jp], S + BHI_OFF + bo);
                LDSM_X4(bl[jp], S + BLO_OFF + bo);
            }
#pragma unroll
            for (int rt = 0; rt < 2; rt++) {
#pragma unroll
                for (int jp = 0; jp < 4; jp++) {
                    MMA16816(acc[rt][jp * 2],     ah[rt], bh[jp][0], bh[jp][1]);
                    MMA16816(acc[rt][jp * 2 + 1], ah[rt], bh[jp][2], bh[jp][3]);
                    MMA16816(acc[rt][jp * 2],     ah[rt], bl[jp][0], bl[jp][1]);
                    MMA16816(acc[rt][jp * 2 + 1], ah[rt], bl[jp][2], bl[jp][3]);
                    MMA16816(acc[rt][jp * 2],     al[rt], bh[jp][0], bh[jp][1]);
                    MMA16816(acc[rt][jp * 2 + 1], al[rt], bh[jp][2], bh[jp][3]);
                }
            }
        }
    }

    /* -------- fused epilogue -------- */
    float negK = g_negK;
    int g = lane >> 2, tg = lane & 3;
    float rowsq[2][2], colsq[8][2];
#pragma unroll
    for (int rt = 0; rt < 2; rt++) {
        rowsq[rt][0] = sqA[rw * 32 + rt * 16 + g];
        rowsq[rt][1] = sqA[rw * 32 + rt * 16 + g + 8];
    }
#pragma unroll
    for (int j = 0; j < 8; j++) {
        colsq[j][0] = sqB[cw * 64 + j * 8 + 2 * tg];
        colsq[j][1] = sqB[cw * 64 + j * 8 + 2 * tg + 1];
    }

    float tsum = 0.f;
#pragma unroll
    for (int rt = 0; rt < 2; rt++) {
#pragma unroll
        for (int j = 0; j < 8; j++) {
#pragma unroll
            for (int e = 0; e < 4; e++) {
                float sq2 = rowsq[rt][e >> 1] + colsq[j][e & 1];
                float L2v = fmaf(-2.f, acc[rt][j][e], sq2);
                float s;
                asm("ex2.approx.f32 %0, %1;" : "=f"(s) : "f"(L2v * negK));
                float s2 = s * s, s4 = s2 * s2, s8 = s4 * s4, s16 = s8 * s8;
                tsum += ((s + s2) + (s4 + s8)) + s16;
            }
        }
    }
#pragma unroll
    for (int o = 16; o > 0; o >>= 1) tsum += __shfl_xor_sync(0xffffffffu, tsum, o);
    if (lane == 0) red[wid] = tsum;
    __syncthreads();
    if (tid == 0) {
        float tot = 0.f;
#pragma unroll
        for (int i = 0; i < 8; i++) tot += red[i];
        double w = (bi == bj) ? 1.0 : 2.0;
        int qidx = (bi < NT2 / 2) ? ((bj < NT2 / 2) ? 0 : 2) : 1;
        atomicAdd(&g_acc[qidx], w * (double)tot);
    }
}

/* ---------------------------------------------------------------- final */
__global__ void k_final(float* out) {
    double bb = (double)BHALF * (double)BHALF;
    out[0] = (float)((g_acc[0] + g_acc[1] - g_acc[2]) / bb);
}

/* ---------------------------------------------------------------- launch */
extern "C" void kernel_launch(void* const* d_in, const int* in_sizes, int n_in,
                              void* d_out, int out_size) {
    const float* src = (const float*)d_in[0];
    const float* tgt = (const float*)d_in[1];
    float* out = (float*)d_out;

    cudaFuncSetAttribute(k_gemm, cudaFuncAttributeMaxDynamicSharedMemorySize, SMEM_TOTAL);

    k_init<<<1, 512>>>();
    k_split<<<NROW * DDIM / 4 / 256, 256>>>(src, tgt);
    k_rownorm<<<NROW / 8, 256>>>(src, tgt);
    k_colsum<<<NROW / 128, 256>>>(src, tgt);
    k_bw<<<1, 512>>>();
    k_gemm<<<NPAIR2, 256, SMEM_TOTAL>>>();
    k_final<<<1, 1>>>(out);
}

// round 4
// speedup vs baseline: 5.9081x; 1.3967x over previous
#include <cuda_runtime.h>
#include <cuda_bf16.h>
#include <math.h>
#include <stdint.h>

#define NROW 8192
#define DDIM 512
#define BHALF 4096

#define TILE 128
#define NT2 (NROW / TILE)            /* 64 */
#define NPAIR2 (NT2 * (NT2 + 1) / 2) /* 2080 */
#define BKC 32                       /* bf16 per K-chunk */
#define NCH (DDIM / BKC)             /* 16 */

#define SQA_OFF 0
#define SQB_OFF 512
#define RED_OFF 1024
#define TILES_OFF 1280
#define ROW_PITCH 80                 /* 32 bf16 = 64B + 16B pad (conflict-free) */
#define MAT_BYTES (TILE * ROW_PITCH) /* 10240 */
#define AHI_OFF 0
#define BHI_OFF (MAT_BYTES)
#define BLO_OFF (2 * MAT_BYTES)
#define STAGE_BYTES (3 * MAT_BYTES)  /* 30720 */
#define NSTAGE 3
#define SMEM_TOTAL (TILES_OFF + NSTAGE * STAGE_BYTES) /* 93440 */

__device__ float  g_sq[NROW];
__device__ float  g_colsum[DDIM];
__device__ float  g_totsq;
__device__ double g_acc[3];
__device__ float  g_negK;            /* -log2(e)/(16*bw) */
__device__ __nv_bfloat16 g_hi[NROW * DDIM];
__device__ __nv_bfloat16 g_lo[NROW * DDIM];

__device__ __forceinline__ uint32_t smem_u32(const void* p) {
    uint32_t a;
    asm("{ .reg .u64 t; cvta.to.shared.u64 t, %1; cvt.u32.u64 %0, t; }"
        : "=r"(a) : "l"(p));
    return a;
}

#define CP_ASYNC16(dst, src) \
    asm volatile("cp.async.cg.shared.global [%0], [%1], 16;" \
                 :: "r"(dst), "l"(src) : "memory")
#define CP_COMMIT() asm volatile("cp.async.commit_group;" ::: "memory")
#define CP_WAIT(n)  asm volatile("cp.async.wait_group %0;" :: "n"(n) : "memory")

#define LDSM_X4(r, a) \
    asm volatile("ldmatrix.sync.aligned.m8n8.x4.shared.b16 {%0,%1,%2,%3}, [%4];" \
                 : "=r"((r)[0]), "=r"((r)[1]), "=r"((r)[2]), "=r"((r)[3]) : "r"(a))

#define MMA16816(acc, a, b0v, b1v) \
    asm volatile("mma.sync.aligned.m16n8k16.row.col.f32.bf16.bf16.f32 " \
                 "{%0,%1,%2,%3},{%4,%5,%6,%7},{%8,%9},{%0,%1,%2,%3};" \
                 : "+f"((acc)[0]), "+f"((acc)[1]), "+f"((acc)[2]), "+f"((acc)[3]) \
                 : "r"((a)[0]), "r"((a)[1]), "r"((a)[2]), "r"((a)[3]), \
                   "r"(b0v), "r"(b1v))

/* ---------------------------------------------------------------- init */
__global__ void k_init() {
    int t = threadIdx.x;
    if (t < DDIM) g_colsum[t] = 0.f;
    if (t == 0) {
        g_totsq = 0.f;
        g_acc[0] = 0.0; g_acc[1] = 0.0; g_acc[2] = 0.0;
    }
}

/* ------------------------------------------------ fused split + rownorm + totsq */
__global__ void k_prep(const float* __restrict__ src, const float* __restrict__ tgt) {
    int warp = threadIdx.x >> 5, lane = threadIdx.x & 31;
    int row = blockIdx.x * 8 + warp;
    const float* base = (row < BHALF) ? src + (size_t)row * DDIM
                                      : tgt + (size_t)(row - BHALF) * DDIM;
    size_t orow = (size_t)row * (DDIM / 4);   /* in float4/uint2 units */
    float s = 0.f;
#pragma unroll
    for (int ch = 0; ch < 4; ch++) {
        float4 v = *(const float4*)(base + ch * 128 + lane * 4);
        s += v.x * v.x + v.y * v.y + v.z * v.z + v.w * v.w;
        __nv_bfloat16 h0 = __float2bfloat16(v.x);
        __nv_bfloat16 h1 = __float2bfloat16(v.y);
        __nv_bfloat16 h2 = __float2bfloat16(v.z);
        __nv_bfloat16 h3 = __float2bfloat16(v.w);
        __nv_bfloat16 l0 = __float2bfloat16(v.x - __bfloat162float(h0));
        __nv_bfloat16 l1 = __float2bfloat16(v.y - __bfloat162float(h1));
        __nv_bfloat16 l2 = __float2bfloat16(v.z - __bfloat162float(h2));
        __nv_bfloat16 l3 = __float2bfloat16(v.w - __bfloat162float(h3));
        __nv_bfloat162 hp0(h0, h1), hp1(h2, h3), lp0(l0, l1), lp1(l2, l3);
        uint2 hv, lv;
        hv.x = *(uint32_t*)&hp0; hv.y = *(uint32_t*)&hp1;
        lv.x = *(uint32_t*)&lp0; lv.y = *(uint32_t*)&lp1;
        ((uint2*)g_hi)[orow + ch * 32 + lane] = hv;
        ((uint2*)g_lo)[orow + ch * 32 + lane] = lv;
    }
#pragma unroll
    for (int o = 16; o > 0; o >>= 1) s += __shfl_xor_sync(0xffffffffu, s, o);
    if (lane == 0) g_sq[row] = s;

    __shared__ float bs[8];
    if (lane == 0) bs[warp] = s;
    __syncthreads();
    if (threadIdx.x == 0) {
        float t = 0.f;
#pragma unroll
        for (int i = 0; i < 8; i++) t += bs[i];
        atomicAdd(&g_totsq, t);
    }
}

/* ---------------------------------------------------------------- column sums */
__global__ void k_colsum(const float* __restrict__ src, const float* __restrict__ tgt) {
    int c = threadIdx.x * 2;
    int r0 = blockIdx.x * 64;
    const float* base = (r0 < BHALF) ? src + (size_t)r0 * DDIM
                                     : tgt + (size_t)(r0 - BHALF) * DDIM;
    float s0 = 0.f, s1 = 0.f;
#pragma unroll 4
    for (int r = 0; r < 64; r++) {
        float2 v = *(const float2*)(base + (size_t)r * DDIM + c);
        s0 += v.x; s1 += v.y;
    }
    atomicAdd(&g_colsum[c], s0);
    atomicAdd(&g_colsum[c + 1], s1);
}

/* ---------------------------------------------------------------- bandwidth */
__global__ void k_bw() {
    __shared__ double wred[16];
    int t = threadIdx.x, lane = t & 31, warp = t >> 5;
    double v = (double)g_colsum[t];
    double p = v * v;
#pragma unroll
    for (int o = 16; o > 0; o >>= 1)
        p += __shfl_xor_sync(0xffffffffu, p, o);
    if (lane == 0) wred[warp] = p;
    __syncthreads();
    if (t == 0) {
        double tot = 0.0;
#pragma unroll
        for (int i = 0; i < 16; i++) tot += wred[i];
        double n = (double)NROW;
        double S = 2.0 * n * (double)g_totsq - 2.0 * tot;
        double bw = S / (n * n - n) / 4.0;
        g_negK = (float)(-1.4426950408889634 / (16.0 * bw));
    }
}

/* ---------------------------------------------------------------- chunk loader */
__device__ __forceinline__ void issue_chunk(uint32_t stage_base, int rowA, int rowB,
                                            int kt, int tid) {
    const char* srcs[3] = {
        (const char*)(g_hi + (size_t)rowA * DDIM),
        (const char*)(g_hi + (size_t)rowB * DDIM),
        (const char*)(g_lo + (size_t)rowB * DDIM)
    };
    int kbyte = kt * (BKC * 2);
#pragma unroll
    for (int m = 0; m < 3; m++) {
        uint32_t dbase = stage_base + m * MAT_BYTES;
#pragma unroll
        for (int i = 0; i < 2; i++) {
            int u = tid + i * 256;
            int r = u >> 2, seg = u & 3;
            const char* src = srcs[m] + (size_t)r * (DDIM * 2) + kbyte + seg * 16;
            uint32_t dst = dbase + r * ROW_PITCH + seg * 16;
            CP_ASYNC16(dst, src);
        }
    }
    CP_COMMIT();
}

/* ---------------------------------------------------------------- main HMMA kernel */
__global__ void __launch_bounds__(256, 1) k_gemm() {
    extern __shared__ char smem[];
    int tid = threadIdx.x;
    int lane = tid & 31, wid = tid >> 5;
    int rw = wid & 3, cw = wid >> 2;

    int t = blockIdx.x;
    int bi = 0, rem = t;
    while (rem >= NT2 - bi) { rem -= NT2 - bi; bi++; }
    int bj = bi + rem;
    int rowA = bi * TILE, rowB = bj * TILE;

    uint32_t sbase = smem_u32(smem);
    float* sqA = (float*)(smem + SQA_OFF);
    float* sqB = (float*)(smem + SQB_OFF);
    float* red = (float*)(smem + RED_OFF);

    if (tid < TILE) {
        sqA[tid] = g_sq[rowA + tid];
        sqB[tid] = g_sq[rowB + tid];
    }

    uint32_t aRow = rw * 32 + (lane & 7) + (lane & 8);
    uint32_t aColH = (lane & 16) >> 1;
    uint32_t bN = cw * 64 + (lane & 7) + ((lane & 16) >> 1);
    uint32_t bKoff = (lane & 8);

    float acc[2][8][4];
#pragma unroll
    for (int r = 0; r < 2; r++)
#pragma unroll
        for (int j = 0; j < 8; j++)
#pragma unroll
            for (int e = 0; e < 4; e++) acc[r][j][e] = 0.f;

    uint32_t tb = sbase + TILES_OFF;
    issue_chunk(tb, rowA, rowB, 0, tid);
    issue_chunk(tb + STAGE_BYTES, rowA, rowB, 1, tid);

    int sidx = 0;           /* stage of kt */
    for (int kt = 0; kt < NCH; kt++) {
        CP_WAIT(1);         /* stage kt complete (kt+1 may still be in flight) */
        __syncthreads();
        if (kt + 2 < NCH) {
            int ns = sidx + 2; if (ns >= NSTAGE) ns -= NSTAGE;
            issue_chunk(tb + ns * STAGE_BYTES, rowA, rowB, kt + 2, tid);
        }

        uint32_t S = tb + sidx * STAGE_BYTES;
#pragma unroll
        for (int ks = 0; ks < 2; ks++) {
            uint32_t k0 = ks * 16;
            uint32_t ah[2][4], bh[4][4], bl[4][4];
#pragma unroll
            for (int rt = 0; rt < 2; rt++) {
                uint32_t ao = (aRow + rt * 16) * ROW_PITCH + (k0 + aColH) * 2;
                LDSM_X4(ah[rt], S + AHI_OFF + ao);
            }
#pragma unroll
            for (int jp = 0; jp < 4; jp++) {
                uint32_t bo = (bN + jp * 16) * ROW_PITCH + (k0 + bKoff) * 2;
                LDSM_X4(bh[jp], S + BHI_OFF + bo);
                LDSM_X4(bl[jp], S + BLO_OFF + bo);
            }
#pragma unroll
            for (int rt = 0; rt < 2; rt++) {
#pragma unroll
                for (int jp = 0; jp < 4; jp++) {
                    MMA16816(acc[rt][jp * 2],     ah[rt], bh[jp][0], bh[jp][1]);
                    MMA16816(acc[rt][jp * 2 + 1], ah[rt], bh[jp][2], bh[jp][3]);
                    MMA16816(acc[rt][jp * 2],     ah[rt], bl[jp][0], bl[jp][1]);
                    MMA16816(acc[rt][jp * 2 + 1], ah[rt], bl[jp][2], bl[jp][3]);
                }
            }
        }
        sidx++; if (sidx >= NSTAGE) sidx = 0;
    }

    /* -------- fused epilogue -------- */
    float negK = g_negK;
    int g = lane >> 2, tg = lane & 3;
    float rowsq[2][2], colsq[8][2];
#pragma unroll
    for (int rt = 0; rt < 2; rt++) {
        rowsq[rt][0] = sqA[rw * 32 + rt * 16 + g];
        rowsq[rt][1] = sqA[rw * 32 + rt * 16 + g + 8];
    }
#pragma unroll
    for (int j = 0; j < 8; j++) {
        colsq[j][0] = sqB[cw * 64 + j * 8 + 2 * tg];
        colsq[j][1] = sqB[cw * 64 + j * 8 + 2 * tg + 1];
    }

    float tsum = 0.f;
#pragma unroll
    for (int rt = 0; rt < 2; rt++) {
#pragma unroll
        for (int j = 0; j < 8; j++) {
#pragma unroll
            for (int e = 0; e < 4; e++) {
                float sq2 = rowsq[rt][e >> 1] + colsq[j][e & 1];
                float L2v = fmaf(-2.f, acc[rt][j][e], sq2);
                float s;
                asm("ex2.approx.f32 %0, %1;" : "=f"(s) : "f"(L2v * negK));
                float s2 = s * s, s4 = s2 * s2, s8 = s4 * s4, s16 = s8 * s8;
                tsum += ((s + s2) + (s4 + s8)) + s16;
            }
        }
    }
#pragma unroll
    for (int o = 16; o > 0; o >>= 1) tsum += __shfl_xor_sync(0xffffffffu, tsum, o);
    if (lane == 0) red[wid] = tsum;
    __syncthreads();
    if (tid == 0) {
        float tot = 0.f;
#pragma unroll
        for (int i = 0; i < 8; i++) tot += red[i];
        double w = (bi == bj) ? 1.0 : 2.0;
        int qidx = (bi < NT2 / 2) ? ((bj < NT2 / 2) ? 0 : 2) : 1;
        atomicAdd(&g_acc[qidx], w * (double)tot);
    }
}

/* ---------------------------------------------------------------- final */
__global__ void k_final(float* out) {
    double bb = (double)BHALF * (double)BHALF;
    out[0] = (float)((g_acc[0] + g_acc[1] - g_acc[2]) / bb);
}

/* ---------------------------------------------------------------- launch */
extern "C" void kernel_launch(void* const* d_in, const int* in_sizes, int n_in,
                              void* d_out, int out_size) {
    const float* src = (const float*)d_in[0];
    const float* tgt = (const float*)d_in[1];
    float* out = (float*)d_out;

    cudaFuncSetAttribute(k_gemm, cudaFuncAttributeMaxDynamicSharedMemorySize, SMEM_TOTAL);

    k_init<<<1, 512>>>();
    k_prep<<<NROW / 8, 256>>>(src, tgt);
    k_colsum<<<NROW / 64, 256>>>(src, tgt);
    k_bw<<<1, 512>>>();
    k_gemm<<<NPAIR2, 256, SMEM_TOTAL>>>();
    k_final<<<1, 1>>>(out);
}

// round 5
// speedup vs baseline: 11.0122x; 1.8639x over previous
#include <cuda_runtime.h>
#include <cuda_fp16.h>
#include <math.h>
#include <stdint.h>

#define NROW 8192
#define DDIM 512
#define BHALF 4096

#define TILE 128
#define NT2 (NROW / TILE)            /* 64 */
#define NPAIR2 (NT2 * (NT2 + 1) / 2) /* 2080 */
#define BKC 32                       /* fp16 per K-chunk */
#define NCH (DDIM / BKC)             /* 16 */

#define SQA_OFF 0
#define SQB_OFF 512
#define RED_OFF 1024
#define TILES_OFF 1280
#define ROW_PITCH 80                 /* 32 fp16 = 64B + 16B pad (conflict-free) */
#define MAT_BYTES (TILE * ROW_PITCH) /* 10240 */
#define A_OFF 0
#define B_OFF (MAT_BYTES)
#define STAGE_BYTES (2 * MAT_BYTES)  /* 20480 */
#define NSTAGE 3
#define SMEM_TOTAL (TILES_OFF + NSTAGE * STAGE_BYTES) /* 62720 */

__device__ float  g_sq[NROW];
__device__ float  g_colsum[DDIM];
__device__ float  g_totsq;
__device__ double g_acc[3];
__device__ float  g_negK;            /* -log2(e)/(16*bw) */
__device__ __half g_h[NROW * DDIM];

__device__ __forceinline__ uint32_t smem_u32(const void* p) {
    uint32_t a;
    asm("{ .reg .u64 t; cvta.to.shared.u64 t, %1; cvt.u32.u64 %0, t; }"
        : "=r"(a) : "l"(p));
    return a;
}

#define CP_ASYNC16(dst, src) \
    asm volatile("cp.async.cg.shared.global [%0], [%1], 16;" \
                 :: "r"(dst), "l"(src) : "memory")
#define CP_COMMIT() asm volatile("cp.async.commit_group;" ::: "memory")
#define CP_WAIT(n)  asm volatile("cp.async.wait_group %0;" :: "n"(n) : "memory")

#define LDSM_X4(r, a) \
    asm volatile("ldmatrix.sync.aligned.m8n8.x4.shared.b16 {%0,%1,%2,%3}, [%4];" \
                 : "=r"((r)[0]), "=r"((r)[1]), "=r"((r)[2]), "=r"((r)[3]) : "r"(a))

#define MMA16816(acc, a, b0v, b1v) \
    asm volatile("mma.sync.aligned.m16n8k16.row.col.f32.f16.f16.f32 " \
                 "{%0,%1,%2,%3},{%4,%5,%6,%7},{%8,%9},{%0,%1,%2,%3};" \
                 : "+f"((acc)[0]), "+f"((acc)[1]), "+f"((acc)[2]), "+f"((acc)[3]) \
                 : "r"((a)[0]), "r"((a)[1]), "r"((a)[2]), "r"((a)[3]), \
                   "r"(b0v), "r"(b1v))

/* ---------------------------------------------------------------- init */
__global__ void k_init() {
    int t = threadIdx.x;
    if (t < DDIM) g_colsum[t] = 0.f;
    if (t == 0) {
        g_totsq = 0.f;
        g_acc[0] = 0.0; g_acc[1] = 0.0; g_acc[2] = 0.0;
    }
}

/* -------------------- fused split(fp16) + rownorm + totsq + colsum -------------------- */
__global__ void k_prep(const float* __restrict__ src, const float* __restrict__ tgt) {
    __shared__ float colacc[8][DDIM];   /* one row per warp */
    __shared__ float bs[8];
    int warp = threadIdx.x >> 5, lane = threadIdx.x & 31;
    int row = blockIdx.x * 8 + warp;
    const float* base = (row < BHALF) ? src + (size_t)row * DDIM
                                      : tgt + (size_t)(row - BHALF) * DDIM;
    size_t orow = (size_t)row * (DDIM / 4);   /* in uint2 (4 halves) units */
    float s = 0.f;
#pragma unroll
    for (int ch = 0; ch < 4; ch++) {
        float4 v = *(const float4*)(base + ch * 128 + lane * 4);
        s += v.x * v.x + v.y * v.y + v.z * v.z + v.w * v.w;
        __half2 p0 = __floats2half2_rn(v.x, v.y);
        __half2 p1 = __floats2half2_rn(v.z, v.w);
        uint2 hv;
        hv.x = *(uint32_t*)&p0; hv.y = *(uint32_t*)&p1;
        ((uint2*)g_h)[orow + ch * 32 + lane] = hv;
        *(float4*)&colacc[warp][ch * 128 + lane * 4] = v;
    }
#pragma unroll
    for (int o = 16; o > 0; o >>= 1) s += __shfl_xor_sync(0xffffffffu, s, o);
    if (lane == 0) { g_sq[row] = s; bs[warp] = s; }
    __syncthreads();

    /* column reduce: thread t owns cols t and t+256 */
    int c0 = threadIdx.x, c1 = threadIdx.x + 256;
    float s0 = 0.f, s1 = 0.f;
#pragma unroll
    for (int w = 0; w < 8; w++) { s0 += colacc[w][c0]; s1 += colacc[w][c1]; }
    atomicAdd(&g_colsum[c0], s0);
    atomicAdd(&g_colsum[c1], s1);

    if (threadIdx.x == 0) {
        float t = 0.f;
#pragma unroll
        for (int i = 0; i < 8; i++) t += bs[i];
        atomicAdd(&g_totsq, t);
    }
}

/* ---------------------------------------------------------------- bandwidth */
__global__ void k_bw() {
    __shared__ double wred[16];
    int t = threadIdx.x, lane = t & 31, warp = t >> 5;
    double v = (double)g_colsum[t];
    double p = v * v;
#pragma unroll
    for (int o = 16; o > 0; o >>= 1)
        p += __shfl_xor_sync(0xffffffffu, p, o);
    if (lane == 0) wred[warp] = p;
    __syncthreads();
    if (t == 0) {
        double tot = 0.0;
#pragma unroll
        for (int i = 0; i < 16; i++) tot += wred[i];
        double n = (double)NROW;
        double S = 2.0 * n * (double)g_totsq - 2.0 * tot;
        double bw = S / (n * n - n) / 4.0;
        g_negK = (float)(-1.4426950408889634 / (16.0 * bw));
    }
}

/* ---------------------------------------------------------------- chunk loader */
__device__ __forceinline__ void issue_chunk(uint32_t stage_base, int rowA, int rowB,
                                            int kt, int tid) {
    const char* srcA = (const char*)(g_h + (size_t)rowA * DDIM);
    const char* srcB = (const char*)(g_h + (size_t)rowB * DDIM);
    int kbyte = kt * (BKC * 2);
#pragma unroll
    for (int i = 0; i < 2; i++) {
        int u = tid + i * 256;
        int r = u >> 2, seg = u & 3;
        size_t go = (size_t)r * (DDIM * 2) + kbyte + seg * 16;
        uint32_t so = r * ROW_PITCH + seg * 16;
        CP_ASYNC16(stage_base + A_OFF + so, srcA + go);
        CP_ASYNC16(stage_base + B_OFF + so, srcB + go);
    }
    CP_COMMIT();
}

/* ---------------------------------------------------------------- main HMMA kernel */
__global__ void __launch_bounds__(256, 2) k_gemm() {
    extern __shared__ char smem[];
    int tid = threadIdx.x;
    int lane = tid & 31, wid = tid >> 5;
    int rw = wid & 3, cw = wid >> 2;

    int t = blockIdx.x;
    int bi = 0, rem = t;
    while (rem >= NT2 - bi) { rem -= NT2 - bi; bi++; }
    int bj = bi + rem;
    int rowA = bi * TILE, rowB = bj * TILE;

    uint32_t sbase = smem_u32(smem);
    float* sqA = (float*)(smem + SQA_OFF);
    float* sqB = (float*)(smem + SQB_OFF);
    float* red = (float*)(smem + RED_OFF);

    if (tid < TILE) {
        sqA[tid] = g_sq[rowA + tid];
        sqB[tid] = g_sq[rowB + tid];
    }

    uint32_t aRow = rw * 32 + (lane & 7) + (lane & 8);
    uint32_t aColH = (lane & 16) >> 1;
    uint32_t bN = cw * 64 + (lane & 7) + ((lane & 16) >> 1);
    uint32_t bKoff = (lane & 8);

    float acc[2][8][4];
#pragma unroll
    for (int r = 0; r < 2; r++)
#pragma unroll
        for (int j = 0; j < 8; j++)
#pragma unroll
            for (int e = 0; e < 4; e++) acc[r][j][e] = 0.f;

    uint32_t tb = sbase + TILES_OFF;
    issue_chunk(tb, rowA, rowB, 0, tid);
    issue_chunk(tb + STAGE_BYTES, rowA, rowB, 1, tid);

    int sidx = 0;
    for (int kt = 0; kt < NCH; kt++) {
        CP_WAIT(1);
        __syncthreads();
        if (kt + 2 < NCH) {
            int ns = sidx + 2; if (ns >= NSTAGE) ns -= NSTAGE;
            issue_chunk(tb + ns * STAGE_BYTES, rowA, rowB, kt + 2, tid);
        }

        uint32_t S = tb + sidx * STAGE_BYTES;
#pragma unroll
        for (int ks = 0; ks < 2; ks++) {
            uint32_t k0 = ks * 16;
            uint32_t ah[2][4], bh[4][4];
#pragma unroll
            for (int rt = 0; rt < 2; rt++) {
                uint32_t ao = (aRow + rt * 16) * ROW_PITCH + (k0 + aColH) * 2;
                LDSM_X4(ah[rt], S + A_OFF + ao);
            }
#pragma unroll
            for (int jp = 0; jp < 4; jp++) {
                uint32_t bo = (bN + jp * 16) * ROW_PITCH + (k0 + bKoff) * 2;
                LDSM_X4(bh[jp], S + B_OFF + bo);
            }
#pragma unroll
            for (int rt = 0; rt < 2; rt++) {
#pragma unroll
                for (int jp = 0; jp < 4; jp++) {
                    MMA16816(acc[rt][jp * 2],     ah[rt], bh[jp][0], bh[jp][1]);
                    MMA16816(acc[rt][jp * 2 + 1], ah[rt], bh[jp][2], bh[jp][3]);
                }
            }
        }
        sidx++; if (sidx >= NSTAGE) sidx = 0;
    }

    /* -------- fused epilogue -------- */
    float negK = g_negK;
    int g = lane >> 2, tg = lane & 3;
    float rowsq[2][2], colsq[8][2];
#pragma unroll
    for (int rt = 0; rt < 2; rt++) {
        rowsq[rt][0] = sqA[rw * 32 + rt * 16 + g];
        rowsq[rt][1] = sqA[rw * 32 + rt * 16 + g + 8];
    }
#pragma unroll
    for (int j = 0; j < 8; j++) {
        colsq[j][0] = sqB[cw * 64 + j * 8 + 2 * tg];
        colsq[j][1] = sqB[cw * 64 + j * 8 + 2 * tg + 1];
    }

    float tsum = 0.f;
#pragma unroll
    for (int rt = 0; rt < 2; rt++) {
#pragma unroll
        for (int j = 0; j < 8; j++) {
#pragma unroll
            for (int e = 0; e < 4; e++) {
                float sq2 = rowsq[rt][e >> 1] + colsq[j][e & 1];
                float L2v = fmaf(-2.f, acc[rt][j][e], sq2);
                float s;
                asm("ex2.approx.f32 %0, %1;" : "=f"(s) : "f"(L2v * negK));
                float s2 = s * s, s4 = s2 * s2, s8 = s4 * s4, s16 = s8 * s8;
                tsum += ((s + s2) + (s4 + s8)) + s16;
            }
        }
    }
#pragma unroll
    for (int o = 16; o > 0; o >>= 1) tsum += __shfl_xor_sync(0xffffffffu, tsum, o);
    if (lane == 0) red[wid] = tsum;
    __syncthreads();
    if (tid == 0) {
        float tot = 0.f;
#pragma unroll
        for (int i = 0; i < 8; i++) tot += red[i];
        double w = (bi == bj) ? 1.0 : 2.0;
        int qidx = (bi < NT2 / 2) ? ((bj < NT2 / 2) ? 0 : 2) : 1;
        atomicAdd(&g_acc[qidx], w * (double)tot);
    }
}

/* ---------------------------------------------------------------- final */
__global__ void k_final(float* out) {
    double bb = (double)BHALF * (double)BHALF;
    out[0] = (float)((g_acc[0] + g_acc[1] - g_acc[2]) / bb);
}

/* ---------------------------------------------------------------- launch */
extern "C" void kernel_launch(void* const* d_in, const int* in_sizes, int n_in,
                              void* d_out, int out_size) {
    const float* src = (const float*)d_in[0];
    const float* tgt = (const float*)d_in[1];
    float* out = (float*)d_out;

    cudaFuncSetAttribute(k_gemm, cudaFuncAttributeMaxDynamicSharedMemorySize, SMEM_TOTAL);

    k_init<<<1, 512>>>();
    k_prep<<<NROW / 8, 256>>>(src, tgt);
    k_bw<<<1, 512>>>();
    k_gemm<<<NPAIR2, 256, SMEM_TOTAL>>>();
    k_final<<<1, 1>>>(out);
}

// round 6
// speedup vs baseline: 11.7740x; 1.0692x over previous
#include <cuda_runtime.h>
#include <cuda_fp16.h>
#include <math.h>
#include <stdint.h>

#define NROW 8192
#define DDIM 512
#define BHALF 4096

#define TILE 128
#define NT2 (NROW / TILE)            /* 64 */
#define NPAIR2 (NT2 * (NT2 + 1) / 2) /* 2080 */
#define BKC 32                       /* fp16 per K-chunk */
#define NCH (DDIM / BKC)             /* 16 */

#define SQA_OFF 0
#define SQB_OFF 512
#define RED_OFF 1024
#define TILES_OFF 1280
#define ROW_PITCH 80                 /* 32 fp16 = 64B + 16B pad (conflict-free) */
#define MAT_BYTES (TILE * ROW_PITCH) /* 10240 */
#define A_OFF 0
#define B_OFF (MAT_BYTES)
#define STAGE_BYTES (2 * MAT_BYTES)  /* 20480 */
#define NSTAGE 3
#define SMEM_TOTAL (TILES_OFF + NSTAGE * STAGE_BYTES) /* 62720 */

__device__ float  g_sq[NROW];
__device__ float  g_colsum[DDIM];
__device__ float  g_totsq;
__device__ double g_acc[3];
__device__ float  g_negK;            /* -log2(e)/(16*bw) */
__device__ __half g_h[NROW * DDIM];

__device__ __forceinline__ uint32_t smem_u32(const void* p) {
    uint32_t a;
    asm("{ .reg .u64 t; cvta.to.shared.u64 t, %1; cvt.u32.u64 %0, t; }"
        : "=r"(a) : "l"(p));
    return a;
}

#define CP_ASYNC16(dst, src) \
    asm volatile("cp.async.cg.shared.global [%0], [%1], 16;" \
                 :: "r"(dst), "l"(src) : "memory")
#define CP_COMMIT() asm volatile("cp.async.commit_group;" ::: "memory")
#define CP_WAIT(n)  asm volatile("cp.async.wait_group %0;" :: "n"(n) : "memory")

#define LDSM_X4(r, a) \
    asm volatile("ldmatrix.sync.aligned.m8n8.x4.shared.b16 {%0,%1,%2,%3}, [%4];" \
                 : "=r"((r)[0]), "=r"((r)[1]), "=r"((r)[2]), "=r"((r)[3]) : "r"(a))

#define MMA16816(acc, a, b0v, b1v) \
    asm volatile("mma.sync.aligned.m16n8k16.row.col.f32.f16.f16.f32 " \
                 "{%0,%1,%2,%3},{%4,%5,%6,%7},{%8,%9},{%0,%1,%2,%3};" \
                 : "+f"((acc)[0]), "+f"((acc)[1]), "+f"((acc)[2]), "+f"((acc)[3]) \
                 : "r"((a)[0]), "r"((a)[1]), "r"((a)[2]), "r"((a)[3]), \
                   "r"(b0v), "r"(b1v))

/* ---------------------------------------------------------------- init */
__global__ void k_init() {
    int t = threadIdx.x;
    if (t < DDIM) g_colsum[t] = 0.f;
    if (t == 0) {
        g_totsq = 0.f;
        g_acc[0] = 0.0; g_acc[1] = 0.0; g_acc[2] = 0.0;
    }
}

/* -------------------- fused split(fp16) + rownorm + totsq + colsum -------------------- */
__global__ void k_prep(const float* __restrict__ src, const float* __restrict__ tgt) {
    __shared__ float colacc[8][DDIM];
    __shared__ float bs[8];
    int warp = threadIdx.x >> 5, lane = threadIdx.x & 31;
    int row = blockIdx.x * 8 + warp;
    const float* base = (row < BHALF) ? src + (size_t)row * DDIM
                                      : tgt + (size_t)(row - BHALF) * DDIM;
    size_t orow = (size_t)row * (DDIM / 4);
    float s = 0.f;
#pragma unroll
    for (int ch = 0; ch < 4; ch++) {
        float4 v = *(const float4*)(base + ch * 128 + lane * 4);
        s += v.x * v.x + v.y * v.y + v.z * v.z + v.w * v.w;
        __half2 p0 = __floats2half2_rn(v.x, v.y);
        __half2 p1 = __floats2half2_rn(v.z, v.w);
        uint2 hv;
        hv.x = *(uint32_t*)&p0; hv.y = *(uint32_t*)&p1;
        ((uint2*)g_h)[orow + ch * 32 + lane] = hv;
        *(float4*)&colacc[warp][ch * 128 + lane * 4] = v;
    }
#pragma unroll
    for (int o = 16; o > 0; o >>= 1) s += __shfl_xor_sync(0xffffffffu, s, o);
    if (lane == 0) { g_sq[row] = s; bs[warp] = s; }
    __syncthreads();

    int c0 = threadIdx.x, c1 = threadIdx.x + 256;
    float s0 = 0.f, s1 = 0.f;
#pragma unroll
    for (int w = 0; w < 8; w++) { s0 += colacc[w][c0]; s1 += colacc[w][c1]; }
    atomicAdd(&g_colsum[c0], s0);
    atomicAdd(&g_colsum[c1], s1);

    if (threadIdx.x == 0) {
        float t = 0.f;
#pragma unroll
        for (int i = 0; i < 8; i++) t += bs[i];
        atomicAdd(&g_totsq, t);
    }
}

/* ---------------------------------------------------------------- bandwidth */
__global__ void k_bw() {
    __shared__ double wred[16];
    int t = threadIdx.x, lane = t & 31, warp = t >> 5;
    double v = (double)g_colsum[t];
    double p = v * v;
#pragma unroll
    for (int o = 16; o > 0; o >>= 1)
        p += __shfl_xor_sync(0xffffffffu, p, o);
    if (lane == 0) wred[warp] = p;
    __syncthreads();
    if (t == 0) {
        double tot = 0.0;
#pragma unroll
        for (int i = 0; i < 16; i++) tot += wred[i];
        double n = (double)NROW;
        double S = 2.0 * n * (double)g_totsq - 2.0 * tot;
        double bw = S / (n * n - n) / 4.0;
        g_negK = (float)(-1.4426950408889634 / (16.0 * bw));
    }
}

/* ---------------------------------------------------------------- chunk loader (128 thr) */
__device__ __forceinline__ void issue_chunk(uint32_t stage_base, int rowA, int rowB,
                                            int kt, int tid) {
    const char* srcA = (const char*)(g_h + (size_t)rowA * DDIM);
    const char* srcB = (const char*)(g_h + (size_t)rowB * DDIM);
    int kbyte = kt * (BKC * 2);
#pragma unroll
    for (int i = 0; i < 4; i++) {
        int u = tid + i * 128;               /* 0..511 */
        int r = u >> 2, seg = u & 3;
        size_t go = (size_t)r * (DDIM * 2) + kbyte + seg * 16;
        uint32_t so = r * ROW_PITCH + seg * 16;
        CP_ASYNC16(stage_base + A_OFF + so, srcA + go);
        CP_ASYNC16(stage_base + B_OFF + so, srcB + go);
    }
    CP_COMMIT();
}

/* ---------------------------------------------------------------- main HMMA kernel */
__global__ void __launch_bounds__(128, 2) k_gemm() {
    extern __shared__ char smem[];
    int tid = threadIdx.x;
    int lane = tid & 31, wid = tid >> 5;
    int wr = wid >> 1, wc = wid & 1;     /* 2x2 grid of 64x64 warp tiles */

    int t = blockIdx.x;
    int bi = 0, rem = t;
    while (rem >= NT2 - bi) { rem -= NT2 - bi; bi++; }
    int bj = bi + rem;
    int rowA = bi * TILE, rowB = bj * TILE;

    uint32_t sbase = smem_u32(smem);
    float* sqA = (float*)(smem + SQA_OFF);
    float* sqB = (float*)(smem + SQB_OFF);
    float* red = (float*)(smem + RED_OFF);

    if (tid < TILE) {
        sqA[tid] = g_sq[rowA + tid];
        sqB[tid] = g_sq[rowB + tid];
    }

    uint32_t aRow = wr * 64 + (lane & 7) + (lane & 8);
    uint32_t aColH = (lane & 16) >> 1;          /* fp16 units */
    uint32_t bN = wc * 64 + (lane & 7) + ((lane & 16) >> 1);
    uint32_t bKoff = (lane & 8);

    float acc[4][8][4];
#pragma unroll
    for (int r = 0; r < 4; r++)
#pragma unroll
        for (int j = 0; j < 8; j++)
#pragma unroll
            for (int e = 0; e < 4; e++) acc[r][j][e] = 0.f;

    uint32_t tb = sbase + TILES_OFF;
    issue_chunk(tb, rowA, rowB, 0, tid);
    issue_chunk(tb + STAGE_BYTES, rowA, rowB, 1, tid);

    uint32_t ah[2][4][4], bh[2][4][4];

    int sidx = 0;
    for (int kt = 0; kt < NCH; kt++) {
        CP_WAIT(1);
        __syncthreads();
        if (kt + 2 < NCH) {
            int ns = sidx + 2; if (ns >= NSTAGE) ns -= NSTAGE;
            issue_chunk(tb + ns * STAGE_BYTES, rowA, rowB, kt + 2, tid);
        }

        uint32_t S = tb + sidx * STAGE_BYTES;

        /* load ks0 fragments */
#pragma unroll
        for (int rt = 0; rt < 4; rt++)
            LDSM_X4(ah[0][rt], S + A_OFF + (aRow + rt * 16) * ROW_PITCH + aColH * 2);
#pragma unroll
        for (int jp = 0; jp < 4; jp++)
            LDSM_X4(bh[0][jp], S + B_OFF + (bN + jp * 16) * ROW_PITCH + bKoff * 2);

        /* prefetch ks1 fragments (overlap with ks0 MMAs) */
#pragma unroll
        for (int rt = 0; rt < 4; rt++)
            LDSM_X4(ah[1][rt], S + A_OFF + (aRow + rt * 16) * ROW_PITCH + (16 + aColH) * 2);
#pragma unroll
        for (int jp = 0; jp < 4; jp++)
            LDSM_X4(bh[1][jp], S + B_OFF + (bN + jp * 16) * ROW_PITCH + (16 + bKoff) * 2);

        /* MMAs ks0 */
#pragma unroll
        for (int rt = 0; rt < 4; rt++)
#pragma unroll
            for (int jp = 0; jp < 4; jp++) {
                MMA16816(acc[rt][jp * 2],     ah[0][rt], bh[0][jp][0], bh[0][jp][1]);
                MMA16816(acc[rt][jp * 2 + 1], ah[0][rt], bh[0][jp][2], bh[0][jp][3]);
            }
        /* MMAs ks1 */
#pragma unroll
        for (int rt = 0; rt < 4; rt++)
#pragma unroll
            for (int jp = 0; jp < 4; jp++) {
                MMA16816(acc[rt][jp * 2],     ah[1][rt], bh[1][jp][0], bh[1][jp][1]);
                MMA16816(acc[rt][jp * 2 + 1], ah[1][rt], bh[1][jp][2], bh[1][jp][3]);
            }

        sidx++; if (sidx >= NSTAGE) sidx = 0;
    }

    /* -------- fused epilogue -------- */
    float negK = g_negK;
    int g = lane >> 2, tg = lane & 3;
    float rowsq[4][2], colsq[8][2];
#pragma unroll
    for (int rt = 0; rt < 4; rt++) {
        rowsq[rt][0] = sqA[wr * 64 + rt * 16 + g];
        rowsq[rt][1] = sqA[wr * 64 + rt * 16 + g + 8];
    }
#pragma unroll
    for (int j = 0; j < 8; j++) {
        colsq[j][0] = sqB[wc * 64 + j * 8 + 2 * tg];
        colsq[j][1] = sqB[wc * 64 + j * 8 + 2 * tg + 1];
    }

    float tsum = 0.f;
#pragma unroll
    for (int rt = 0; rt < 4; rt++) {
#pragma unroll
        for (int j = 0; j < 8; j++) {
#pragma unroll
            for (int e = 0; e < 4; e++) {
                float sq2 = rowsq[rt][e >> 1] + colsq[j][e & 1];
                float L2v = fmaf(-2.f, acc[rt][j][e], sq2);
                float s;
                asm("ex2.approx.f32 %0, %1;" : "=f"(s) : "f"(L2v * negK));
                float s2 = s * s, s4 = s2 * s2, s8 = s4 * s4, s16 = s8 * s8;
                tsum += ((s + s2) + (s4 + s8)) + s16;
            }
        }
    }
#pragma unroll
    for (int o = 16; o > 0; o >>= 1) tsum += __shfl_xor_sync(0xffffffffu, tsum, o);
    if (lane == 0) red[wid] = tsum;
    __syncthreads();
    if (tid == 0) {
        float tot = red[0] + red[1] + red[2] + red[3];
        double w = (bi == bj) ? 1.0 : 2.0;
        int qidx = (bi < NT2 / 2) ? ((bj < NT2 / 2) ? 0 : 2) : 1;
        atomicAdd(&g_acc[qidx], w * (double)tot);
    }
}

/* ---------------------------------------------------------------- final */
__global__ void k_final(float* out) {
    double bb = (double)BHALF * (double)BHALF;
    out[0] = (float)((g_acc[0] + g_acc[1] - g_acc[2]) / bb);
}

/* ---------------------------------------------------------------- launch */
extern "C" void kernel_launch(void* const* d_in, const int* in_sizes, int n_in,
                              void* d_out, int out_size) {
    const float* src = (const float*)d_in[0];
    const float* tgt = (const float*)d_in[1];
    float* out = (float*)d_out;

    cudaFuncSetAttribute(k_gemm, cudaFuncAttributeMaxDynamicSharedMemorySize, SMEM_TOTAL);

    k_init<<<1, 512>>>();
    k_prep<<<NROW / 8, 256>>>(src, tgt);
    k_bw<<<1, 512>>>();
    k_gemm<<<NPAIR2, 128, SMEM_TOTAL>>>();
    k_final<<<1, 1>>>(out);
}